// round 9
// baseline (speedup 1.0000x reference)
#include <cuda_runtime.h>
#include <cuda_bf16.h>
#include <cstdint>

// ---------------------------------------------------------------------------
// g_Bf: W1 bf16 fragments, coalesced uint4 per (ks, t, lane):
//   uint4 index (ks*7 + t)*32 + lane, lane = nrow*4 + q, n = t*8 + nrow
//   bf16[half*2+par]   = hi of W1[k = ks*16 + half*8 + q*2 + par][n]
//   bf16[4+half*2+par] = lo
// ---------------------------------------------------------------------------
static __device__ __align__(16) __nv_bfloat16 g_Bf[32 * 7 * 32 * 8];  // 114688 B
static __device__ __align__(16) float g_W2[112];  // [56][2], rows >= 50 zero
static __device__ __align__(8)  float g_b1[56];   // zero-padded
static __device__ __align__(8)  float g_b2[2];

// ---------------- kernel 1: materialize W1/W2/biases from MPO cores ----------
__global__ void build_weights(const float* __restrict__ A1, const float* __restrict__ A2,
                              const float* __restrict__ A3, const float* __restrict__ A4,
                              const float* __restrict__ A5, const float* __restrict__ b1,
                              const float* __restrict__ B1, const float* __restrict__ B2,
                              const float* __restrict__ B3, const float* __restrict__ b2) {
    __shared__ float sL[500];    // [i][j][p2][v]
    __shared__ float sR1[200];   // [p3][l][m][x]
    __shared__ float sRt[5000];  // [p2][k][w][l][m][x]
    const int t = threadIdx.x;

    for (int e = t; e < 200; e += 256) {
        int x = e & 1, m = (e >> 1) & 1, l = (e >> 2) % 5, p3 = e / 20;
        float s = 0.f;
        for (int p4 = 0; p4 < 10; ++p4)
            s += A4[((p3 * 5 + l) * 10 + p4) * 2 + x] * A5[p4 * 2 + m];
        sR1[e] = s;
    }
    for (int e = t; e < 500; e += 256) {
        int v = e % 5, p2 = (e / 5) % 10, j = (e / 50) % 5, i = e / 250;
        float s = 0.f;
        for (int p1 = 0; p1 < 10; ++p1)
            s += A1[i * 10 + p1] * A2[((p1 * 5 + j) * 10 + p2) * 5 + v];
        sL[e] = s;
    }
    __syncthreads();
    for (int e = t; e < 5000; e += 256) {
        int x = e & 1, m = (e >> 1) & 1, l = (e >> 2) % 5;
        int w = (e / 20) % 5, k = (e / 100) % 5, p2 = e / 500;
        float s = 0.f;
        for (int p3 = 0; p3 < 10; ++p3)
            s += A3[((p2 * 5 + k) * 10 + p3) * 5 + w] * sR1[((p3 * 5 + l) * 2 + m) * 2 + x];
        sRt[e] = s;
    }
    __syncthreads();

    const int kbeg = blockIdx.x * 32;   // 16 CTAs cover k 0..511
    for (int e = t; e < 32 * 56; e += 256) {
        const int n = e % 56;
        const int k = kbeg + e / 56;
        float val = 0.f;
        if (k < 500 && n < 50) {
            int m = k & 1, l = (k >> 1) % 5, kk = (k / 10) % 5, j = (k / 50) % 5, i = k / 250;
            int x = n & 1, w = (n >> 1) % 5, v = n / 10;
            for (int p2 = 0; p2 < 10; ++p2)
                val += sL[((i * 5 + j) * 10 + p2) * 5 + v] *
                       sRt[((((p2 * 5 + kk) * 5 + w) * 5 + l) * 2 + m) * 2 + x];
        }
        __nv_bfloat16 hi = __float2bfloat16(val);
        __nv_bfloat16 lo = __float2bfloat16(val - __bfloat162float(hi));
        const int tt = n >> 3, nr = n & 7;
        const int ks = k >> 4, kk16 = k & 15;
        const int half = kk16 >> 3, q = (kk16 >> 1) & 3, par = kk16 & 1;
        const int base = ((ks * 7 + tt) * 32 + (nr * 4 + q)) * 8;
        g_Bf[base + half * 2 + par] = hi;
        g_Bf[base + 4 + half * 2 + par] = lo;
    }

    if (blockIdx.x == 0) {
        for (int e = t; e < 56; e += 256) g_b1[e] = (e < 50) ? b1[e] : 0.f;
        if (t < 2) g_b2[t] = b2[t];
        for (int e = t; e < 112; e += 256) {
            const int v = e & 1, r = e >> 1;
            float s = 0.f;
            if (r < 50) {
                int i = r / 25, j = (r / 5) % 5, kq = r % 5;
                for (int p1 = 0; p1 < 10; ++p1)
                    for (int p2 = 0; p2 < 10; ++p2)
                        s += B1[i * 10 + p1] * B2[((p1 * 5 + j) * 10 + p2) * 2 + v] *
                             B3[p2 * 5 + kq];
            }
            g_W2[e] = s;
        }
    }
}

// ---------------- main kernel helpers ----------------
__device__ __forceinline__ uint32_t smem_u32(const void* p) {
    uint32_t a;
    asm("{ .reg .u64 t; cvta.to.shared.u64 t, %1; cvt.u32.u64 %0, t; }" : "=r"(a) : "l"(p));
    return a;
}
__device__ __forceinline__ void cp16(uint32_t dst, const void* src) {
    asm volatile("cp.async.cg.shared.global [%0], [%1], 16;" :: "r"(dst), "l"(src) : "memory");
}
__device__ __forceinline__ void cp16z(uint32_t dst, const void* src) {
    asm volatile("cp.async.cg.shared.global [%0], [%1], 16, 0;" :: "r"(dst), "l"(src) : "memory");
}
__device__ __forceinline__ void split2(float vx, float vy, uint32_t& h, uint32_t& l) {
    __nv_bfloat162 hb = __floats2bfloat162_rn(vx, vy);
    float rx = vx - __bfloat162float(hb.x);
    float ry = vy - __bfloat162float(hb.y);
    __nv_bfloat162 lb = __floats2bfloat162_rn(rx, ry);
    h = (uint32_t)__bfloat16_as_ushort(hb.x) | ((uint32_t)__bfloat16_as_ushort(hb.y) << 16);
    l = (uint32_t)__bfloat16_as_ushort(lb.x) | ((uint32_t)__bfloat16_as_ushort(lb.y) << 16);
}
__device__ __forceinline__ void mma16816(float* d, uint32_t a0, uint32_t a1,
                                         uint32_t a2, uint32_t a3,
                                         uint32_t b0, uint32_t b1) {
    asm volatile(
        "mma.sync.aligned.m16n8k16.row.col.f32.bf16.bf16.f32 "
        "{%0,%1,%2,%3}, {%4,%5,%6,%7}, {%8,%9}, {%0,%1,%2,%3};"
        : "+f"(d[0]), "+f"(d[1]), "+f"(d[2]), "+f"(d[3])
        : "r"(a0), "r"(a1), "r"(a2), "r"(a3), "r"(b0), "r"(b1));
}

// ---- smem layout ----
// x: per-warp 3-stage ring, 16 rows x 20 floats per stage (conflict-free pad).
// B: CTA-shared 3-stage ring, 3584 B per stage.
static constexpr int ROW_F   = 20;
static constexpr int STAGES  = 3;
static constexpr int STAGE_F = 16 * ROW_F;              // 320 floats
static constexpr int XW_F    = STAGES * STAGE_F;        // 960 floats / warp
static constexpr int O_B_F   = 8 * XW_F;                // 7680
static constexpr int BSTG_F  = 896;                     // 3584 B per B stage
static constexpr int SMEM_TOTAL = (O_B_F + STAGES * BSTG_F) * 4;  // 41472 B

__device__ __forceinline__ void load_x_chunk(uint32_t wstage_b, const float* xw,
                                             int ks, int lane) {
    #pragma unroll
    for (int i = 0; i < 2; ++i) {
        const int c = lane + 32 * i;
        const int rowl = c >> 2, c4 = c & 3;
        const int kb = ks * 16 + c4 * 4;
        const uint32_t dst = wstage_b + (uint32_t)(rowl * ROW_F + c4 * 4) * 4u;
        if (kb + 4 <= 500) cp16(dst, xw + (size_t)rowl * 500 + kb);
        else               cp16z(dst, xw);
    }
}

// ---------------- kernel 2: fused forward ----------------
// 256 threads = 8 warps; warp owns 16 rows x 56 cols; CTA = 128 rows.
// 3 CTAs/SM (85-reg cap) for latency hiding. One barrier per k-step;
// chunk ks+S-1 fetched into the slot consumed at ks-1 (fenced by barrier).
__global__ void __launch_bounds__(256, 3)
tn_forward(const float* __restrict__ x, float* __restrict__ out) {
    extern __shared__ float sm[];
    const uint32_t sbase = smem_u32(sm);
    const int tid = threadIdx.x;
    const int warp = tid >> 5, lane = tid & 31;
    const int q = lane & 3, nrow = lane >> 2;

    const size_t row0 = (size_t)blockIdx.x * 128;
    const float* xw = x + (row0 + (size_t)warp * 16) * 500;
    const uint32_t xwbase = sbase + (uint32_t)warp * XW_F * 4u;
    const uint32_t bbase = sbase + (uint32_t)O_B_F * 4u;
    const char* gB = reinterpret_cast<const char*>(g_Bf);

    // prologue: fetch chunks 0..S-2 into slots 0..S-2
    #pragma unroll
    for (int s = 0; s < STAGES - 1; ++s) {
        load_x_chunk(xwbase + s * STAGE_F * 4, xw, s, lane);
        if (tid < 224) cp16(bbase + s * BSTG_F * 4 + tid * 16, gB + s * 3584 + tid * 16);
        asm volatile("cp.async.commit_group;" ::: "memory");
    }

    float acc[7][4];
    #pragma unroll
    for (int t = 0; t < 7; ++t)
        acc[t][0] = acc[t][1] = acc[t][2] = acc[t][3] = 0.f;

    const float* wsx = sm + warp * XW_F;

    for (int ks = 0; ks < 32; ++ks) {
        const int slot = ks % STAGES;
        asm volatile("cp.async.wait_group %0;" :: "n"(STAGES - 2) : "memory");
        __syncthreads();

        // fetch chunk ks+S-1 into slot (ks-1) mod S (already consumed)
        const int c = ks + STAGES - 1;
        if (c < 32) {
            const int fslot = c % STAGES;
            load_x_chunk(xwbase + fslot * STAGE_F * 4, xw, c, lane);
            if (tid < 224)
                cp16(bbase + fslot * BSTG_F * 4 + tid * 16, gB + c * 3584 + tid * 16);
        }
        asm volatile("cp.async.commit_group;" ::: "memory");

        // consume
        const uint4* bst = reinterpret_cast<const uint4*>(sm + O_B_F + slot * BSTG_F);
        const float* st = wsx + slot * STAGE_F;

        const float2 u00 = *reinterpret_cast<const float2*>(st + nrow * ROW_F + 2 * q);
        const float2 u10 = *reinterpret_cast<const float2*>(st + (nrow + 8) * ROW_F + 2 * q);
        const float2 u02 = *reinterpret_cast<const float2*>(st + nrow * ROW_F + 8 + 2 * q);
        const float2 u12 = *reinterpret_cast<const float2*>(st + (nrow + 8) * ROW_F + 8 + 2 * q);
        uint32_t ah0, ah1, ah2, ah3, al0, al1, al2, al3;
        split2(u00.x, u00.y, ah0, al0);
        split2(u10.x, u10.y, ah1, al1);
        split2(u02.x, u02.y, ah2, al2);
        split2(u12.x, u12.y, ah3, al3);

        #pragma unroll
        for (int t = 0; t < 7; ++t) {
            const uint4 bf = bst[t * 32 + lane];
            mma16816(acc[t], ah0, ah1, ah2, ah3, bf.x, bf.y);  // hi*hi
            mma16816(acc[t], ah0, ah1, ah2, ah3, bf.z, bf.w);  // hi*lo
            mma16816(acc[t], al0, al1, al2, al3, bf.x, bf.y);  // lo*hi
        }
    }

    // epilogue: bias + relu + layer2 (56 -> 2), quad reduce, store
    const float b20 = g_b2[0], b21 = g_b2[1];
    const int kq = q * 2;
    float s00 = 0.f, s01 = 0.f, s10 = 0.f, s11 = 0.f;
    #pragma unroll
    for (int t = 0; t < 7; ++t) {
        const int n0 = t * 8 + kq;
        const float2 bv = *reinterpret_cast<const float2*>(g_b1 + n0);
        const float4 wv = *reinterpret_cast<const float4*>(g_W2 + 2 * n0);
        float h;
        h = fmaxf(acc[t][0] + bv.x, 0.f); s00 = fmaf(h, wv.x, s00); s01 = fmaf(h, wv.y, s01);
        h = fmaxf(acc[t][1] + bv.y, 0.f); s00 = fmaf(h, wv.z, s00); s01 = fmaf(h, wv.w, s01);
        h = fmaxf(acc[t][2] + bv.x, 0.f); s10 = fmaf(h, wv.x, s10); s11 = fmaf(h, wv.y, s11);
        h = fmaxf(acc[t][3] + bv.y, 0.f); s10 = fmaf(h, wv.z, s10); s11 = fmaf(h, wv.w, s11);
    }
    #pragma unroll
    for (int d = 1; d <= 2; d <<= 1) {
        s00 += __shfl_xor_sync(0xffffffffu, s00, d);
        s01 += __shfl_xor_sync(0xffffffffu, s01, d);
        s10 += __shfl_xor_sync(0xffffffffu, s10, d);
        s11 += __shfl_xor_sync(0xffffffffu, s11, d);
    }
    if (q == 0) {
        const size_t r = row0 + warp * 16 + nrow;
        *reinterpret_cast<float2*>(out + 2 * r) = make_float2(s00 + b20, s01 + b21);
        *reinterpret_cast<float2*>(out + 2 * (r + 8)) = make_float2(s10 + b20, s11 + b21);
    }
}

extern "C" void kernel_launch(void* const* d_in, const int* in_sizes, int n_in,
                              void* d_out, int out_size) {
    const float* x = (const float*)d_in[0];
    build_weights<<<16, 256>>>(
        (const float*)d_in[1], (const float*)d_in[2], (const float*)d_in[3],
        (const float*)d_in[4], (const float*)d_in[5], (const float*)d_in[6],
        (const float*)d_in[7], (const float*)d_in[8], (const float*)d_in[9],
        (const float*)d_in[10]);
    cudaFuncSetAttribute(tn_forward, cudaFuncAttributeMaxDynamicSharedMemorySize, SMEM_TOTAL);
    tn_forward<<<512, 256, SMEM_TOTAL>>>(x, (float*)d_out);
}

// round 10
// speedup vs baseline: 1.0321x; 1.0321x over previous
#include <cuda_runtime.h>
#include <cuda_bf16.h>
#include <cstdint>

// ---------------------------------------------------------------------------
// g_Bf: W1 bf16 fragments, coalesced uint4 per (ks, t, lane):
//   uint4 index (ks*7 + t)*32 + lane, lane = nrow*4 + q, n = t*8 + nrow
//   bf16[half*2+par]   = hi of W1[k = ks*16 + half*8 + q*2 + par][n]
//   bf16[4+half*2+par] = lo
// Built by CTAs 0..15 of the single fused kernel; others spin on g_done.
// ---------------------------------------------------------------------------
static __device__ __align__(16) __nv_bfloat16 g_Bf[32 * 7 * 32 * 8];  // 114688 B
static __device__ __align__(16) float g_W2[112];  // [56][2], rows >= 50 zero
static __device__ __align__(8)  float g_b1[56];   // zero-padded
static __device__ __align__(8)  float g_b2[2];
static __device__ int g_done = 0;   // builder completion count (reset at exit)
static __device__ int g_exit = 0;   // CTA exit count (reset at exit)

// ---------------- helpers ----------------
__device__ __forceinline__ uint32_t smem_u32(const void* p) {
    uint32_t a;
    asm("{ .reg .u64 t; cvta.to.shared.u64 t, %1; cvt.u32.u64 %0, t; }" : "=r"(a) : "l"(p));
    return a;
}
__device__ __forceinline__ void cp16(uint32_t dst, const void* src) {
    asm volatile("cp.async.cg.shared.global [%0], [%1], 16;" :: "r"(dst), "l"(src) : "memory");
}
__device__ __forceinline__ void cp16z(uint32_t dst, const void* src) {
    asm volatile("cp.async.cg.shared.global [%0], [%1], 16, 0;" :: "r"(dst), "l"(src) : "memory");
}
__device__ __forceinline__ void split2(float vx, float vy, uint32_t& h, uint32_t& l) {
    __nv_bfloat162 hb = __floats2bfloat162_rn(vx, vy);
    float rx = vx - __bfloat162float(hb.x);
    float ry = vy - __bfloat162float(hb.y);
    __nv_bfloat162 lb = __floats2bfloat162_rn(rx, ry);
    h = (uint32_t)__bfloat16_as_ushort(hb.x) | ((uint32_t)__bfloat16_as_ushort(hb.y) << 16);
    l = (uint32_t)__bfloat16_as_ushort(lb.x) | ((uint32_t)__bfloat16_as_ushort(lb.y) << 16);
}
__device__ __forceinline__ void mma16816(float* d, uint32_t a0, uint32_t a1,
                                         uint32_t a2, uint32_t a3,
                                         uint32_t b0, uint32_t b1) {
    asm volatile(
        "mma.sync.aligned.m16n8k16.row.col.f32.bf16.bf16.f32 "
        "{%0,%1,%2,%3}, {%4,%5,%6,%7}, {%8,%9}, {%0,%1,%2,%3};"
        : "+f"(d[0]), "+f"(d[1]), "+f"(d[2]), "+f"(d[3])
        : "r"(a0), "r"(a1), "r"(a2), "r"(a3), "r"(b0), "r"(b1));
}

// ---- smem layout (floats) ----
// x: per-warp 3-stage ring, 32 rows x 20 floats per stage (conflict-free pad).
// B: CTA-shared 3-stage ring, 3584 B per stage.
// builder scratch (used only by CTAs 0..15, before the mainloop's B region use).
static constexpr int ROW_F   = 20;
static constexpr int STAGES  = 3;
static constexpr int STAGE_F = 32 * ROW_F;              // 640 floats
static constexpr int XW_F    = STAGES * STAGE_F;        // 1920 floats / warp
static constexpr int O_B_F   = 8 * XW_F;                // 15360
static constexpr int BSTG_F  = 896;                     // 3584 B per B stage
static constexpr int O_BLD   = O_B_F + STAGES * BSTG_F; // 18048
static constexpr int O_SL    = O_BLD;                   // 500
static constexpr int O_SR1   = O_SL + 500;              // 200
static constexpr int O_SRT   = O_SR1 + 200;             // 5000
static constexpr int SMEM_F  = O_SRT + 5000;            // 23748
static constexpr int SMEM_TOTAL = SMEM_F * 4;           // 94992 B (2 CTA/SM ok)

__device__ __forceinline__ void load_x_chunk(uint32_t wstage_b, const float* xw,
                                             int ks, int lane) {
    #pragma unroll
    for (int i = 0; i < 4; ++i) {
        const int c = lane + 32 * i;
        const int rowl = c >> 2, c4 = c & 3;
        const int kb = ks * 16 + c4 * 4;
        const uint32_t dst = wstage_b + (uint32_t)(rowl * ROW_F + c4 * 4) * 4u;
        if (kb + 4 <= 500) cp16(dst, xw + (size_t)rowl * 500 + kb);
        else               cp16z(dst, xw);
    }
}

// ---------------- single fused kernel ----------------
// 256 CTAs x 256 threads (single wave at 2 CTA/SM). Warp owns 32 rows x 56 cols.
__global__ void __launch_bounds__(256, 2)
tn_forward(const float* __restrict__ x, float* __restrict__ out,
           const float* __restrict__ A1, const float* __restrict__ A2,
           const float* __restrict__ A3, const float* __restrict__ A4,
           const float* __restrict__ A5, const float* __restrict__ b1,
           const float* __restrict__ B1, const float* __restrict__ B2,
           const float* __restrict__ B3, const float* __restrict__ b2) {
    extern __shared__ float sm[];
    const uint32_t sbase = smem_u32(sm);
    const int tid = threadIdx.x;
    const int warp = tid >> 5, lane = tid & 31;
    const int q = lane & 3, nrow = lane >> 2;

    const size_t row0 = (size_t)blockIdx.x * 256;
    const float* xw = x + (row0 + (size_t)warp * 32) * 500;
    const uint32_t xwbase = sbase + (uint32_t)warp * XW_F * 4u;
    const uint32_t bbase = sbase + (uint32_t)O_B_F * 4u;
    const char* gB = reinterpret_cast<const char*>(g_Bf);

    // issue x prefetch for chunks 0..S-2 (uncommitted; overlaps weight build)
    #pragma unroll
    for (int s = 0; s < STAGES - 1; ++s)
        load_x_chunk(xwbase + s * STAGE_F * 4, xw, s, lane);

    // ---- CTAs 0..15: build the weight table (16-way parallel over k) ----
    if (blockIdx.x < 16) {
        float* sL  = sm + O_SL;
        float* sR1 = sm + O_SR1;
        float* sRt = sm + O_SRT;
        for (int e = tid; e < 200; e += 256) {
            int xo = e & 1, m = (e >> 1) & 1, l = (e >> 2) % 5, p3 = e / 20;
            float s = 0.f;
            for (int p4 = 0; p4 < 10; ++p4)
                s += A4[((p3 * 5 + l) * 10 + p4) * 2 + xo] * A5[p4 * 2 + m];
            sR1[e] = s;
        }
        for (int e = tid; e < 500; e += 256) {
            int v = e % 5, p2 = (e / 5) % 10, j = (e / 50) % 5, i = e / 250;
            float s = 0.f;
            for (int p1 = 0; p1 < 10; ++p1)
                s += A1[i * 10 + p1] * A2[((p1 * 5 + j) * 10 + p2) * 5 + v];
            sL[e] = s;
        }
        __syncthreads();
        for (int e = tid; e < 5000; e += 256) {
            int xo = e & 1, m = (e >> 1) & 1, l = (e >> 2) % 5;
            int w = (e / 20) % 5, k = (e / 100) % 5, p2 = e / 500;
            float s = 0.f;
            for (int p3 = 0; p3 < 10; ++p3)
                s += A3[((p2 * 5 + k) * 10 + p3) * 5 + w] *
                     sR1[((p3 * 5 + l) * 2 + m) * 2 + xo];
            sRt[e] = s;
        }
        __syncthreads();

        const int kbeg = blockIdx.x * 32;
        for (int e = tid; e < 32 * 56; e += 256) {
            const int n = e % 56;
            const int k = kbeg + e / 56;
            float val = 0.f;
            if (k < 500 && n < 50) {
                int m = k & 1, l = (k >> 1) % 5, kk = (k / 10) % 5, j = (k / 50) % 5,
                    i = k / 250;
                int xo = n & 1, w = (n >> 1) % 5, v = n / 10;
                for (int p2 = 0; p2 < 10; ++p2)
                    val += sL[((i * 5 + j) * 10 + p2) * 5 + v] *
                           sRt[((((p2 * 5 + kk) * 5 + w) * 5 + l) * 2 + m) * 2 + xo];
            }
            __nv_bfloat16 hi = __float2bfloat16(val);
            __nv_bfloat16 lo = __float2bfloat16(val - __bfloat162float(hi));
            const int tt = n >> 3, nr = n & 7;
            const int ks = k >> 4, kk16 = k & 15;
            const int half = kk16 >> 3, qq = (kk16 >> 1) & 3, par = kk16 & 1;
            const int base = ((ks * 7 + tt) * 32 + (nr * 4 + qq)) * 8;
            g_Bf[base + half * 2 + par] = hi;
            g_Bf[base + 4 + half * 2 + par] = lo;
        }
        if (blockIdx.x == 0) {
            for (int e = tid; e < 56; e += 256) g_b1[e] = (e < 50) ? b1[e] : 0.f;
            if (tid < 2) g_b2[tid] = b2[tid];
            for (int e = tid; e < 112; e += 256) {
                const int v = e & 1, r = e >> 1;
                float s = 0.f;
                if (r < 50) {
                    int i = r / 25, j = (r / 5) % 5, kq2 = r % 5;
                    for (int p1 = 0; p1 < 10; ++p1)
                        for (int p2 = 0; p2 < 10; ++p2)
                            s += B1[i * 10 + p1] * B2[((p1 * 5 + j) * 10 + p2) * 2 + v] *
                                 B3[p2 * 5 + kq2];
                }
                g_W2[e] = s;
            }
        }
        __syncthreads();
        if (tid == 0) {
            __threadfence();
            atomicAdd(&g_done, 1);
        }
    }

    // ---- all CTAs: wait for the 16 builders ----
    if (tid == 0) {
        while (atomicAdd(&g_done, 0) < 16) __nanosleep(64);
        __threadfence();
    }
    __syncthreads();

    // B prefetch for chunks 0..S-2; commit groups: g0={x0,x1,B0}, g1={B1}
    #pragma unroll
    for (int s = 0; s < STAGES - 1; ++s) {
        if (tid < 224) cp16(bbase + s * BSTG_F * 4 + tid * 16, gB + s * 3584 + tid * 16);
        asm volatile("cp.async.commit_group;" ::: "memory");
    }

    float acc[2][7][4];
    #pragma unroll
    for (int rb = 0; rb < 2; ++rb)
        #pragma unroll
        for (int t = 0; t < 7; ++t)
            acc[rb][t][0] = acc[rb][t][1] = acc[rb][t][2] = acc[rb][t][3] = 0.f;

    const float* wsx = sm + warp * XW_F;

    for (int ks = 0; ks < 32; ++ks) {
        const int slot = ks % STAGES;
        asm volatile("cp.async.wait_group %0;" :: "n"(STAGES - 2) : "memory");
        __syncthreads();

        // fetch chunk ks+S-1 into slot (ks-1) mod S (already consumed)
        const int c = ks + STAGES - 1;
        if (c < 32) {
            const int fslot = c % STAGES;
            load_x_chunk(xwbase + fslot * STAGE_F * 4, xw, c, lane);
            if (tid < 224)
                cp16(bbase + fslot * BSTG_F * 4 + tid * 16, gB + c * 3584 + tid * 16);
        }
        asm volatile("cp.async.commit_group;" ::: "memory");

        // consume
        const uint4* bst = reinterpret_cast<const uint4*>(sm + O_B_F + slot * BSTG_F);
        uint4 bf[7];
        #pragma unroll
        for (int t = 0; t < 7; ++t)
            bf[t] = bst[t * 32 + lane];

        const float* st = wsx + slot * STAGE_F;
        #pragma unroll
        for (int rb = 0; rb < 2; ++rb) {
            const int rl = rb * 16 + nrow;
            const float2 u00 = *reinterpret_cast<const float2*>(st + rl * ROW_F + 2 * q);
            const float2 u10 = *reinterpret_cast<const float2*>(st + (rl + 8) * ROW_F + 2 * q);
            const float2 u02 = *reinterpret_cast<const float2*>(st + rl * ROW_F + 8 + 2 * q);
            const float2 u12 = *reinterpret_cast<const float2*>(st + (rl + 8) * ROW_F + 8 + 2 * q);
            uint32_t ah0, ah1, ah2, ah3, al0, al1, al2, al3;
            split2(u00.x, u00.y, ah0, al0);
            split2(u10.x, u10.y, ah1, al1);
            split2(u02.x, u02.y, ah2, al2);
            split2(u12.x, u12.y, ah3, al3);
            #pragma unroll
            for (int t = 0; t < 7; ++t) {
                mma16816(acc[rb][t], ah0, ah1, ah2, ah3, bf[t].x, bf[t].y);  // hi*hi
                mma16816(acc[rb][t], ah0, ah1, ah2, ah3, bf[t].z, bf[t].w);  // hi*lo
                mma16816(acc[rb][t], al0, al1, al2, al3, bf[t].x, bf[t].y);  // lo*hi
            }
        }
    }

    // epilogue: bias + relu + layer2 (56 -> 2), quad reduce, store
    const float b20 = g_b2[0], b21 = g_b2[1];
    const int kq = q * 2;
    #pragma unroll
    for (int rb = 0; rb < 2; ++rb) {
        float s00 = 0.f, s01 = 0.f, s10 = 0.f, s11 = 0.f;
        #pragma unroll
        for (int t = 0; t < 7; ++t) {
            const int n0 = t * 8 + kq;
            const float2 bv = *reinterpret_cast<const float2*>(g_b1 + n0);
            const float4 wv = *reinterpret_cast<const float4*>(g_W2 + 2 * n0);
            float h;
            h = fmaxf(acc[rb][t][0] + bv.x, 0.f); s00 = fmaf(h, wv.x, s00); s01 = fmaf(h, wv.y, s01);
            h = fmaxf(acc[rb][t][1] + bv.y, 0.f); s00 = fmaf(h, wv.z, s00); s01 = fmaf(h, wv.w, s01);
            h = fmaxf(acc[rb][t][2] + bv.x, 0.f); s10 = fmaf(h, wv.x, s10); s11 = fmaf(h, wv.y, s11);
            h = fmaxf(acc[rb][t][3] + bv.y, 0.f); s10 = fmaf(h, wv.z, s10); s11 = fmaf(h, wv.w, s11);
        }
        #pragma unroll
        for (int d = 1; d <= 2; d <<= 1) {
            s00 += __shfl_xor_sync(0xffffffffu, s00, d);
            s01 += __shfl_xor_sync(0xffffffffu, s01, d);
            s10 += __shfl_xor_sync(0xffffffffu, s10, d);
            s11 += __shfl_xor_sync(0xffffffffu, s11, d);
        }
        if (q == 0) {
            const size_t r = row0 + warp * 32 + rb * 16 + nrow;
            *reinterpret_cast<float2*>(out + 2 * r) = make_float2(s00 + b20, s01 + b21);
            *reinterpret_cast<float2*>(out + 2 * (r + 8)) = make_float2(s10 + b20, s11 + b21);
        }
    }

    // reset flags for the next graph replay (last CTA out turns off the lights)
    __syncthreads();
    if (tid == 0) {
        if (atomicAdd(&g_exit, 1) == (int)gridDim.x - 1) {
            atomicExch(&g_done, 0);
            atomicExch(&g_exit, 0);
            __threadfence();
        }
    }
}

extern "C" void kernel_launch(void* const* d_in, const int* in_sizes, int n_in,
                              void* d_out, int out_size) {
    cudaFuncSetAttribute(tn_forward, cudaFuncAttributeMaxDynamicSharedMemorySize, SMEM_TOTAL);
    tn_forward<<<256, 256, SMEM_TOTAL>>>(
        (const float*)d_in[0], (float*)d_out,
        (const float*)d_in[1], (const float*)d_in[2], (const float*)d_in[3],
        (const float*)d_in[4], (const float*)d_in[5], (const float*)d_in[6],
        (const float*)d_in[7], (const float*)d_in[8], (const float*)d_in[9],
        (const float*)d_in[10]);
}

// round 12
// speedup vs baseline: 1.2920x; 1.2519x over previous
#include <cuda_runtime.h>
#include <cuda_bf16.h>
#include <cstdint>

// ---------------------------------------------------------------------------
// g_Bf: W1 bf16 fragments, coalesced uint4 per (ks, t, lane):
//   uint4 index e = (ks*7 + tt)*32 + lane, lane = nr*4 + fq, n = tt*8 + nr
//   bf16[e*8 + half*2+par]   = hi of W1[k = ks*16 + half*8 + fq*2 + par][n]
//   bf16[e*8 + 4+half*2+par] = lo
// Total 7168 uint4 = 114688 B. Each CTA builds uint4s [bid*28, bid*28+28)
// (112 worker threads, one (k,n,half,par) cell each); grid flag gates reads.
// ---------------------------------------------------------------------------
static __device__ __align__(16) __nv_bfloat16 g_Bf[7168 * 8];  // 114688 B
static __device__ __align__(16) float g_W2[112];  // [56][2], rows >= 50 zero
static __device__ __align__(8)  float g_b1[56];   // zero-padded
static __device__ __align__(8)  float g_b2[2];
static __device__ unsigned g_done = 0;  // builder completions (reset at exit)
static __device__ unsigned g_exit = 0;  // CTA exits (reset at exit)

// ---------------- helpers ----------------
__device__ __forceinline__ uint32_t smem_u32(const void* p) {
    uint32_t a;
    asm("{ .reg .u64 t; cvta.to.shared.u64 t, %1; cvt.u32.u64 %0, t; }" : "=r"(a) : "l"(p));
    return a;
}
__device__ __forceinline__ void cp16(uint32_t dst, const void* src) {
    asm volatile("cp.async.cg.shared.global [%0], [%1], 16;" :: "r"(dst), "l"(src) : "memory");
}
__device__ __forceinline__ void cp16z(uint32_t dst, const void* src) {
    asm volatile("cp.async.cg.shared.global [%0], [%1], 16, 0;" :: "r"(dst), "l"(src) : "memory");
}
__device__ __forceinline__ void split2(float vx, float vy, uint32_t& h, uint32_t& l) {
    __nv_bfloat162 hb = __floats2bfloat162_rn(vx, vy);
    float rx = vx - __bfloat162float(hb.x);
    float ry = vy - __bfloat162float(hb.y);
    __nv_bfloat162 lb = __floats2bfloat162_rn(rx, ry);
    h = (uint32_t)__bfloat16_as_ushort(hb.x) | ((uint32_t)__bfloat16_as_ushort(hb.y) << 16);
    l = (uint32_t)__bfloat16_as_ushort(lb.x) | ((uint32_t)__bfloat16_as_ushort(lb.y) << 16);
}
__device__ __forceinline__ void mma16816(float* d, uint32_t a0, uint32_t a1,
                                         uint32_t a2, uint32_t a3,
                                         uint32_t b0, uint32_t b1) {
    asm volatile(
        "mma.sync.aligned.m16n8k16.row.col.f32.bf16.bf16.f32 "
        "{%0,%1,%2,%3}, {%4,%5,%6,%7}, {%8,%9}, {%0,%1,%2,%3};"
        : "+f"(d[0]), "+f"(d[1]), "+f"(d[2]), "+f"(d[3])
        : "r"(a0), "r"(a1), "r"(a2), "r"(a3), "r"(b0), "r"(b1));
}

// ---- smem layout (floats) ----
// x: per-warp 3-stage ring, 32 rows x 20 floats per stage (conflict-free pad).
// B: CTA-shared 3-stage ring, 3584 B per stage.
static constexpr int ROW_F   = 20;
static constexpr int STAGES  = 3;
static constexpr int STAGE_F = 32 * ROW_F;              // 640 floats
static constexpr int XW_F    = STAGES * STAGE_F;        // 1920 floats / warp
static constexpr int O_B_F   = 8 * XW_F;                // 15360
static constexpr int BSTG_F  = 896;                     // 3584 B per B stage
static constexpr int SMEM_TOTAL = (O_B_F + STAGES * BSTG_F) * 4;  // 72192 B

__device__ __forceinline__ void load_x_chunk(uint32_t wstage_b, const float* xw,
                                             int ks, int lane) {
    #pragma unroll
    for (int i = 0; i < 4; ++i) {
        const int c = lane + 32 * i;
        const int rowl = c >> 2, c4 = c & 3;
        const int kb = ks * 16 + c4 * 4;
        const uint32_t dst = wstage_b + (uint32_t)(rowl * ROW_F + c4 * 4) * 4u;
        if (kb + 4 <= 500) cp16(dst, xw + (size_t)rowl * 500 + kb);
        else               cp16z(dst, xw);
    }
}

// ---------------- single fused kernel ----------------
// 256 CTAs x 256 threads (single wave at 2 CTA/SM). Warp owns 32 rows x 56 cols.
__global__ void __launch_bounds__(256, 2)
tn_forward(const float* __restrict__ x, float* __restrict__ out,
           const float* __restrict__ A1, const float* __restrict__ A2,
           const float* __restrict__ A3, const float* __restrict__ A4,
           const float* __restrict__ A5, const float* __restrict__ b1,
           const float* __restrict__ B1, const float* __restrict__ B2,
           const float* __restrict__ B3, const float* __restrict__ b2) {
    extern __shared__ float sm[];
    const uint32_t sbase = smem_u32(sm);
    const int tid = threadIdx.x;
    const int warp = tid >> 5, lane = tid & 31;
    const int q = lane & 3, nrow = lane >> 2;

    const size_t row0 = (size_t)blockIdx.x * 256;
    const float* xw = x + (row0 + (size_t)warp * 32) * 500;
    const uint32_t xwbase = sbase + (uint32_t)warp * XW_F * 4u;
    const uint32_t bbase = sbase + (uint32_t)O_B_F * 4u;
    const char* gB = reinterpret_cast<const char*>(g_Bf);

    // issue x prefetch for chunks 0..S-2 (uncommitted; overlaps weight build)
    #pragma unroll
    for (int s = 0; s < STAGES - 1; ++s)
        load_x_chunk(xwbase + s * STAGE_F * 4, xw, s, lane);

    // ---- distributed weight build: this CTA owns uint4s [bid*28, bid*28+28) ----
    // One (k,n,half,par) cell per worker thread: ~310 register FMAs, no staging.
    if (tid < 112) {
        const int u = tid >> 2, hp = tid & 3;
        const int e = blockIdx.x * 28 + u;
        const int lane_f = e & 31, tt = (e >> 5) % 7, ks = (e >> 5) / 7;
        const int nr = lane_f >> 2, fq = lane_f & 3;
        const int n = tt * 8 + nr;
        const int k = ks * 16 + (hp >> 1) * 8 + fq * 2 + (hp & 1);
        float val = 0.f;
        if (k < 500 && n < 50) {
            const int i = k / 250, j = (k / 50) % 5, kk = (k / 10) % 5;
            const int l = (k >> 1) % 5, m = k & 1;
            const int v = n / 10, w = (n >> 1) % 5, xo = n & 1;
            float sR1[10];
            #pragma unroll
            for (int p3 = 0; p3 < 10; ++p3) {
                float s = 0.f;
                #pragma unroll
                for (int p4 = 0; p4 < 10; ++p4)
                    s += A4[((p3 * 5 + l) * 10 + p4) * 2 + xo] * A5[p4 * 2 + m];
                sR1[p3] = s;
            }
            #pragma unroll
            for (int p2 = 0; p2 < 10; ++p2) {
                float rt = 0.f, sl = 0.f;
                #pragma unroll
                for (int p3 = 0; p3 < 10; ++p3)
                    rt += A3[((p2 * 5 + kk) * 10 + p3) * 5 + w] * sR1[p3];
                #pragma unroll
                for (int p1 = 0; p1 < 10; ++p1)
                    sl += A1[i * 10 + p1] * A2[((p1 * 5 + j) * 10 + p2) * 5 + v];
                val += sl * rt;
            }
        }
        const __nv_bfloat16 hi = __float2bfloat16(val);
        const __nv_bfloat16 lo = __float2bfloat16(val - __bfloat162float(hi));
        g_Bf[e * 8 + hp] = hi;
        g_Bf[e * 8 + 4 + hp] = lo;
    }
    // CTA 0: W2 / b1 / b2 (consumed only after the same flag gate)
    if (blockIdx.x == 0) {
        if (tid >= 128 && tid < 240) {
            const int t2 = tid - 128;
            const int v = t2 & 1, r = t2 >> 1;
            float s = 0.f;
            if (r < 50) {
                const int i = r / 25, j = (r / 5) % 5, kq2 = r % 5;
                #pragma unroll
                for (int p1 = 0; p1 < 10; ++p1)
                    #pragma unroll
                    for (int p2 = 0; p2 < 10; ++p2)
                        s += B1[i * 10 + p1] * B2[((p1 * 5 + j) * 10 + p2) * 2 + v] *
                             B3[p2 * 5 + kq2];
            }
            g_W2[t2] = s;
        }
        if (tid >= 240 && tid < 242) g_b2[tid - 240] = b2[tid - 240];
        if (tid < 56) {
            // builders tid<56 also write b1 after their fragment (cheap)
            g_b1[tid] = (tid < 50) ? b1[tid] : 0.f;
        }
    }
    __syncthreads();
    if (tid == 0)
        asm volatile("red.release.gpu.global.add.u32 [%0], 1;" :: "l"(&g_done) : "memory");

    // ---- grid barrier: wait for all 256 builders ----
    if (tid == 0) {
        unsigned v;
        while (true) {
            asm volatile("ld.acquire.gpu.global.u32 %0, [%1];" : "=r"(v) : "l"(&g_done) : "memory");
            if (v >= gridDim.x) break;
            __nanosleep(64);
        }
    }
    __syncthreads();

    // B prefetch for chunks 0..S-2; group0 = {x0,x1,B0}, group1 = {B1}
    #pragma unroll
    for (int s = 0; s < STAGES - 1; ++s) {
        if (tid < 224) cp16(bbase + s * BSTG_F * 4 + tid * 16, gB + s * 3584 + tid * 16);
        asm volatile("cp.async.commit_group;" ::: "memory");
    }

    float acc[2][7][4];
    #pragma unroll
    for (int rb = 0; rb < 2; ++rb)
        #pragma unroll
        for (int t = 0; t < 7; ++t)
            acc[rb][t][0] = acc[rb][t][1] = acc[rb][t][2] = acc[rb][t][3] = 0.f;

    const float* wsx = sm + warp * XW_F;

    for (int ks = 0; ks < 32; ++ks) {
        const int slot = ks % STAGES;
        asm volatile("cp.async.wait_group %0;" :: "n"(STAGES - 2) : "memory");
        __syncthreads();

        // fetch chunk ks+S-1 into the slot consumed at ks-1 (barrier-fenced)
        const int c = ks + STAGES - 1;
        if (c < 32) {
            const int fslot = c % STAGES;
            load_x_chunk(xwbase + fslot * STAGE_F * 4, xw, c, lane);
            if (tid < 224)
                cp16(bbase + fslot * BSTG_F * 4 + tid * 16, gB + c * 3584 + tid * 16);
        }
        asm volatile("cp.async.commit_group;" ::: "memory");

        // consume
        const uint4* bst = reinterpret_cast<const uint4*>(sm + O_B_F + slot * BSTG_F);
        uint4 bf[7];
        #pragma unroll
        for (int t = 0; t < 7; ++t)
            bf[t] = bst[t * 32 + lane];

        const float* st = wsx + slot * STAGE_F;
        #pragma unroll
        for (int rb = 0; rb < 2; ++rb) {
            const int rl = rb * 16 + nrow;
            const float2 u00 = *reinterpret_cast<const float2*>(st + rl * ROW_F + 2 * q);
            const float2 u10 = *reinterpret_cast<const float2*>(st + (rl + 8) * ROW_F + 2 * q);
            const float2 u02 = *reinterpret_cast<const float2*>(st + rl * ROW_F + 8 + 2 * q);
            const float2 u12 = *reinterpret_cast<const float2*>(st + (rl + 8) * ROW_F + 8 + 2 * q);
            uint32_t ah0, ah1, ah2, ah3, al0, al1, al2, al3;
            split2(u00.x, u00.y, ah0, al0);
            split2(u10.x, u10.y, ah1, al1);
            split2(u02.x, u02.y, ah2, al2);
            split2(u12.x, u12.y, ah3, al3);
            #pragma unroll
            for (int t = 0; t < 7; ++t) {
                mma16816(acc[rb][t], ah0, ah1, ah2, ah3, bf[t].x, bf[t].y);  // hi*hi
                mma16816(acc[rb][t], ah0, ah1, ah2, ah3, bf[t].z, bf[t].w);  // hi*lo
                mma16816(acc[rb][t], al0, al1, al2, al3, bf[t].x, bf[t].y);  // lo*hi
            }
        }
    }

    // epilogue: bias + relu + layer2 (56 -> 2), quad reduce, store
    const float b20 = g_b2[0], b21 = g_b2[1];
    const int kq = q * 2;
    #pragma unroll
    for (int rb = 0; rb < 2; ++rb) {
        float s00 = 0.f, s01 = 0.f, s10 = 0.f, s11 = 0.f;
        #pragma unroll
        for (int t = 0; t < 7; ++t) {
            const int n0 = t * 8 + kq;
            const float2 bv = *reinterpret_cast<const float2*>(g_b1 + n0);
            const float4 wv = *reinterpret_cast<const float4*>(g_W2 + 2 * n0);
            float h;
            h = fmaxf(acc[rb][t][0] + bv.x, 0.f); s00 = fmaf(h, wv.x, s00); s01 = fmaf(h, wv.y, s01);
            h = fmaxf(acc[rb][t][1] + bv.y, 0.f); s00 = fmaf(h, wv.z, s00); s01 = fmaf(h, wv.w, s01);
            h = fmaxf(acc[rb][t][2] + bv.x, 0.f); s10 = fmaf(h, wv.x, s10); s11 = fmaf(h, wv.y, s11);
            h = fmaxf(acc[rb][t][3] + bv.y, 0.f); s10 = fmaf(h, wv.z, s10); s11 = fmaf(h, wv.w, s11);
        }
        #pragma unroll
        for (int d = 1; d <= 2; d <<= 1) {
            s00 += __shfl_xor_sync(0xffffffffu, s00, d);
            s01 += __shfl_xor_sync(0xffffffffu, s01, d);
            s10 += __shfl_xor_sync(0xffffffffu, s10, d);
            s11 += __shfl_xor_sync(0xffffffffu, s11, d);
        }
        if (q == 0) {
            const size_t r = row0 + warp * 32 + rb * 16 + nrow;
            *reinterpret_cast<float2*>(out + 2 * r) = make_float2(s00 + b20, s01 + b21);
            *reinterpret_cast<float2*>(out + 2 * (r + 8)) = make_float2(s10 + b20, s11 + b21);
        }
    }

    // reset flags for the next graph replay (last CTA out turns off the lights)
    __syncthreads();
    if (tid == 0) {
        const unsigned prev = atomicAdd(&g_exit, 1u);
        if (prev == gridDim.x - 1) {
            atomicExch(&g_done, 0u);
            atomicExch(&g_exit, 0u);
            __threadfence();
        }
    }
}

extern "C" void kernel_launch(void* const* d_in, const int* in_sizes, int n_in,
                              void* d_out, int out_size) {
    cudaFuncSetAttribute(tn_forward, cudaFuncAttributeMaxDynamicSharedMemorySize, SMEM_TOTAL);
    tn_forward<<<256, 256, SMEM_TOTAL>>>(
        (const float*)d_in[0], (float*)d_out,
        (const float*)d_in[1], (const float*)d_in[2], (const float*)d_in[3],
        (const float*)d_in[4], (const float*)d_in[5], (const float*)d_in[6],
        (const float*)d_in[7], (const float*)d_in[8], (const float*)d_in[9],
        (const float*)d_in[10]);
}